// round 3
// baseline (speedup 1.0000x reference)
#include <cuda_runtime.h>
#include <math.h>

#define CB 8
#define CT 1024
#define CE 1024
#define CH 16
#define CD 64

// Scratch (device globals: allocation-free). Layout [b*H+h][t][64] contiguous.
__device__ float g_Q  [CB*CH*CT*CD];
__device__ float g_V  [CB*CH*CT*CD];
__device__ float g_NW [CB*CH*CT*CD];
__device__ float g_ATT[CB*CH*CT*CD];

// ---------------------------------------------------------------------------
// Per-head 64x64 projection: Y[t,e] = sum_d X[t,d] * W[h,d,e]
// One block = one (b,h) and a 64-row t-tile. 256 threads, 4x4 register tiles.
// ---------------------------------------------------------------------------
__global__ __launch_bounds__(256) void proj64_kernel(
    const float* __restrict__ X, const float* __restrict__ W,
    float* __restrict__ Y, int x_rs, int y_rs, int x_bte, int y_bte)
{
    __shared__ float Xs[64 * 68];   // transposed [d][t], padded
    __shared__ float Ws[64 * 64];   // [d][e]
    const int bh = blockIdx.y;
    const int b = bh >> 4, h = bh & 15;
    const int t0 = blockIdx.x << 6;
    const float* Xp = X + (x_bte ? ((size_t)b * CT * CE + h * 64)
                                 : ((size_t)bh * CT * 64)) + (size_t)t0 * x_rs;
    float* Yp = Y + (y_bte ? ((size_t)b * CT * CE + h * 64)
                           : ((size_t)bh * CT * 64)) + (size_t)t0 * y_rs;
    const float* Wp = W + h * 4096;
    const int tid = threadIdx.x;

    const float4* W4 = (const float4*)Wp;
    float4* Ws4 = (float4*)Ws;
#pragma unroll
    for (int k = 0; k < 4; k++) Ws4[tid + k * 256] = W4[tid + k * 256];
#pragma unroll
    for (int k = 0; k < 4; k++) {
        int i = tid + k * 256;
        int r = i >> 4, d4 = i & 15;
        float4 v = *(const float4*)(Xp + (size_t)r * x_rs + d4 * 4);
        Xs[(d4 * 4 + 0) * 68 + r] = v.x;
        Xs[(d4 * 4 + 1) * 68 + r] = v.y;
        Xs[(d4 * 4 + 2) * 68 + r] = v.z;
        Xs[(d4 * 4 + 3) * 68 + r] = v.w;
    }
    __syncthreads();

    const int ty = tid >> 4, tx = tid & 15;
    float acc[4][4];
#pragma unroll
    for (int i = 0; i < 4; i++)
#pragma unroll
        for (int j = 0; j < 4; j++) acc[i][j] = 0.f;

#pragma unroll 8
    for (int d = 0; d < 64; d++) {
        float4 a4 = *(const float4*)&Xs[d * 68 + ty * 4];
        float4 w4 = *(const float4*)&Ws[d * 64 + tx * 4];
        float a[4] = {a4.x, a4.y, a4.z, a4.w};
        float w[4] = {w4.x, w4.y, w4.z, w4.w};
#pragma unroll
        for (int i = 0; i < 4; i++)
#pragma unroll
            for (int j = 0; j < 4; j++) acc[i][j] += a[i] * w[j];
    }
#pragma unroll
    for (int i = 0; i < 4; i++) {
        float4 r = make_float4(acc[i][0], acc[i][1], acc[i][2], acc[i][3]);
        *(float4*)(Yp + (size_t)(ty * 4 + i) * y_rs + tx * 4) = r;
    }
}

// ---------------------------------------------------------------------------
// RNN: one block per (b,h) chain. 64 threads, thread e owns output row e of
// W_sum = W_ih + W_hh in registers. Hidden state double-buffered in smem,
// one __syncthreads per step. h1 uses W_ih only (per reference).
// ---------------------------------------------------------------------------
__global__ __launch_bounds__(64) void rnn_kernel(
    const float* __restrict__ target,
    const float* __restrict__ W_ih, const float* __restrict__ W_hh,
    const float* __restrict__ b_ih, const float* __restrict__ b_hh,
    float* __restrict__ NW)
{
    const int bh = blockIdx.x;
    const int b = bh >> 4, h = bh & 15;
    const int e = threadIdx.x;
    __shared__ float hs[2][64];

    float w[64];
    const float* wih = W_ih + h * 4096 + e * 64;
#pragma unroll
    for (int j = 0; j < 64; j++) w[j] = wih[j];
    const float bsum = b_ih[h * 64 + e] + b_hh[h * 64 + e];

    // k0 = target[b, 0, h*64 + :]
    hs[0][e] = target[(size_t)b * CT * CE + h * 64 + e];
    __syncthreads();

    float a0 = bsum, a1 = 0.f, a2 = 0.f, a3 = 0.f;
#pragma unroll
    for (int j = 0; j < 16; j++) {
        float4 hv = *(const float4*)&hs[0][j * 4];
        a0 += hv.x * w[j * 4 + 0];
        a1 += hv.y * w[j * 4 + 1];
        a2 += hv.z * w[j * 4 + 2];
        a3 += hv.w * w[j * 4 + 3];
    }
    float hcur = tanhf((a0 + a1) + (a2 + a3));
    float* nwp = NW + (size_t)bh * CT * 64 + e;
    nwp[0] = hcur;
    hs[1][e] = hcur;

    const float* whh = W_hh + h * 4096 + e * 64;
#pragma unroll
    for (int j = 0; j < 64; j++) w[j] += whh[j];   // W_sum for remaining steps
    __syncthreads();

    int p = 1;
    for (int t = 1; t < CT; t++) {
        float b0 = bsum, b1 = 0.f, b2 = 0.f, b3 = 0.f;
#pragma unroll
        for (int j = 0; j < 16; j++) {
            float4 hv = *(const float4*)&hs[p][j * 4];
            b0 += hv.x * w[j * 4 + 0];
            b1 += hv.y * w[j * 4 + 1];
            b2 += hv.z * w[j * 4 + 2];
            b3 += hv.w * w[j * 4 + 3];
        }
        float hn = tanhf((b0 + b1) + (b2 + b3));
        nwp[(size_t)t * 64] = hn;
        hs[p ^ 1][e] = hn;
        __syncthreads();
        p ^= 1;
    }
}

// ---------------------------------------------------------------------------
// Flash attention (fp32). Block = (b,h, 64-row q-tile). 256 threads,
// Bk=64 key tiles streamed with online softmax. Scale = 1/(sqrt(D)*sqrt(T)).
// Dynamic smem: Qs,Ks transposed [d][row] pad-68; Vs [j][e] pad-68; Ps [i][j].
// ---------------------------------------------------------------------------
#define ASM_STRIDE 68
#define ASM_REGION (64 * ASM_STRIDE)

__global__ __launch_bounds__(256) void attn_kernel(
    const float* __restrict__ Q, const float* __restrict__ K,
    const float* __restrict__ V, float* __restrict__ O)
{
    extern __shared__ float smf[];
    float* Qs = smf;
    float* Ks = smf + ASM_REGION;
    float* Vs = smf + 2 * ASM_REGION;
    float* Ps = smf + 3 * ASM_REGION;

    const int bh = blockIdx.y;
    const int q0 = blockIdx.x << 6;
    const float* Qp = Q + ((size_t)bh * CT + q0) * 64;
    const float* Kp = K + (size_t)bh * CT * 64;
    const float* Vp = V + (size_t)bh * CT * 64;
    float* Op = O + ((size_t)bh * CT + q0) * 64;

    const int tid = threadIdx.x;
    const int ty = tid >> 4, tx = tid & 15;

    // Q tile -> transposed smem
#pragma unroll
    for (int k = 0; k < 4; k++) {
        int i = tid + k * 256;
        int r = i >> 4, d4 = i & 15;
        float4 v = *(const float4*)(Qp + r * 64 + d4 * 4);
        Qs[(d4 * 4 + 0) * ASM_STRIDE + r] = v.x;
        Qs[(d4 * 4 + 1) * ASM_STRIDE + r] = v.y;
        Qs[(d4 * 4 + 2) * ASM_STRIDE + r] = v.z;
        Qs[(d4 * 4 + 3) * ASM_STRIDE + r] = v.w;
    }

    float m_i[4], l_i[4], o_acc[4][4];
#pragma unroll
    for (int i = 0; i < 4; i++) {
        m_i[i] = -1e30f;
        l_i[i] = 0.f;
#pragma unroll
        for (int c = 0; c < 4; c++) o_acc[i][c] = 0.f;
    }
    const float scale = 1.0f / 256.0f;   // 1/(8*32)

    for (int kt = 0; kt < 16; kt++) {
        const float* Kt = Kp + kt * 64 * 64;
        const float* Vt = Vp + kt * 64 * 64;
#pragma unroll
        for (int k = 0; k < 4; k++) {
            int i = tid + k * 256;
            int r = i >> 4, d4 = i & 15;
            float4 kv = *(const float4*)(Kt + r * 64 + d4 * 4);
            Ks[(d4 * 4 + 0) * ASM_STRIDE + r] = kv.x;
            Ks[(d4 * 4 + 1) * ASM_STRIDE + r] = kv.y;
            Ks[(d4 * 4 + 2) * ASM_STRIDE + r] = kv.z;
            Ks[(d4 * 4 + 3) * ASM_STRIDE + r] = kv.w;
            float4 vv = *(const float4*)(Vt + r * 64 + d4 * 4);
            *(float4*)&Vs[r * ASM_STRIDE + d4 * 4] = vv;
        }
        __syncthreads();

        // S = Q @ K^T (4x4 per thread)
        float s[4][4];
#pragma unroll
        for (int i = 0; i < 4; i++)
#pragma unroll
            for (int j = 0; j < 4; j++) s[i][j] = 0.f;
#pragma unroll 8
        for (int d = 0; d < 64; d++) {
            float4 a4 = *(const float4*)&Qs[d * ASM_STRIDE + ty * 4];
            float4 b4 = *(const float4*)&Ks[d * ASM_STRIDE + tx * 4];
            float a[4] = {a4.x, a4.y, a4.z, a4.w};
            float bb[4] = {b4.x, b4.y, b4.z, b4.w};
#pragma unroll
            for (int i = 0; i < 4; i++)
#pragma unroll
                for (int j = 0; j < 4; j++) s[i][j] += a[i] * bb[j];
        }

        // online softmax update per q-row (row shared by the 16 tx threads)
#pragma unroll
        for (int i = 0; i < 4; i++) {
#pragma unroll
            for (int j = 0; j < 4; j++) s[i][j] *= scale;
            float rm = fmaxf(fmaxf(s[i][0], s[i][1]), fmaxf(s[i][2], s[i][3]));
#pragma unroll
            for (int off = 8; off >= 1; off >>= 1)
                rm = fmaxf(rm, __shfl_xor_sync(0xffffffffu, rm, off, 16));
            float mn = fmaxf(m_i[i], rm);
            float corr = __expf(m_i[i] - mn);
            float rs = 0.f;
#pragma unroll
            for (int j = 0; j < 4; j++) {
                s[i][j] = __expf(s[i][j] - mn);
                rs += s[i][j];
            }
#pragma unroll
            for (int off = 8; off >= 1; off >>= 1)
                rs += __shfl_xor_sync(0xffffffffu, rs, off, 16);
            l_i[i] = l_i[i] * corr + rs;
            m_i[i] = mn;
#pragma unroll
            for (int c = 0; c < 4; c++) o_acc[i][c] *= corr;
        }

        // P -> smem [i][j] (vectorized, conflict-free)
#pragma unroll
        for (int i = 0; i < 4; i++)
            *(float4*)&Ps[(ty * 4 + i) * ASM_STRIDE + tx * 4] =
                make_float4(s[i][0], s[i][1], s[i][2], s[i][3]);
        __syncthreads();

        // O += P @ V
#pragma unroll 4
        for (int j4 = 0; j4 < 16; j4++) {
            float pa[4][4], vb[4][4];
#pragma unroll
            for (int i = 0; i < 4; i++) {
                float4 t4 = *(const float4*)&Ps[(ty * 4 + i) * ASM_STRIDE + j4 * 4];
                pa[i][0] = t4.x; pa[i][1] = t4.y; pa[i][2] = t4.z; pa[i][3] = t4.w;
            }
#pragma unroll
            for (int jj = 0; jj < 4; jj++) {
                float4 t4 = *(const float4*)&Vs[(j4 * 4 + jj) * ASM_STRIDE + tx * 4];
                vb[jj][0] = t4.x; vb[jj][1] = t4.y; vb[jj][2] = t4.z; vb[jj][3] = t4.w;
            }
#pragma unroll
            for (int i = 0; i < 4; i++)
#pragma unroll
                for (int jj = 0; jj < 4; jj++)
#pragma unroll
                    for (int c = 0; c < 4; c++)
                        o_acc[i][c] += pa[i][jj] * vb[jj][c];
        }
        __syncthreads();
    }

#pragma unroll
    for (int i = 0; i < 4; i++) {
        float inv = 1.0f / l_i[i];
        float4 r = make_float4(o_acc[i][0] * inv, o_acc[i][1] * inv,
                               o_acc[i][2] * inv, o_acc[i][3] * inv);
        *(float4*)(Op + (size_t)(ty * 4 + i) * 64 + tx * 4) = r;
    }
}

// ---------------------------------------------------------------------------
extern "C" void kernel_launch(void* const* d_in, const int* in_sizes, int n_in,
                              void* d_out, int out_size)
{
    (void)in_sizes; (void)n_in; (void)out_size;
    const float* source = (const float*)d_in[0];
    const float* target = (const float*)d_in[1];
    const float* W_q    = (const float*)d_in[2];
    const float* W_v    = (const float*)d_in[3];
    const float* W_o    = (const float*)d_in[4];
    const float* W_ih   = (const float*)d_in[5];
    const float* W_hh   = (const float*)d_in[6];
    const float* b_ih   = (const float*)d_in[7];
    const float* b_hh   = (const float*)d_in[8];
    float* out = (float*)d_out;

    void *pQ, *pV, *pNW, *pATT;
    cudaGetSymbolAddress(&pQ,  g_Q);
    cudaGetSymbolAddress(&pV,  g_V);
    cudaGetSymbolAddress(&pNW, g_NW);
    cudaGetSymbolAddress(&pATT, g_ATT);
    float* Qb   = (float*)pQ;
    float* Vb   = (float*)pV;
    float* NWb  = (float*)pNW;
    float* ATTb = (float*)pATT;

    const dim3 pgrid(CT / 64, CB * CH);

    // Q/V head projections (independent of RNN — all on default stream)
    proj64_kernel<<<pgrid, 256>>>(source, W_q, Qb, CE, 64, 1, 0);
    proj64_kernel<<<pgrid, 256>>>(target, W_v, Vb, CE, 64, 1, 0);

    // RNN hidden-state sequence (the attention "keys")
    rnn_kernel<<<CB * CH, 64>>>(target, W_ih, W_hh, b_ih, b_hh, NWb);

    // Flash attention
    const int attn_smem = 4 * ASM_REGION * (int)sizeof(float);  // 69632 B
    cudaFuncSetAttribute(attn_kernel,
                         cudaFuncAttributeMaxDynamicSharedMemorySize, attn_smem);
    attn_kernel<<<pgrid, 256, attn_smem>>>(Qb, NWb, Vb, ATTb);

    // Output projection back to (B, T, E)
    proj64_kernel<<<pgrid, 256>>>(ATTb, W_o, out, 64, CE, 0, 1);
}

// round 4
// speedup vs baseline: 2.0626x; 2.0626x over previous
#include <cuda_runtime.h>
#include <math.h>

#define CB 8
#define CT 1024
#define CE 1024
#define CH 16
#define CD 64

// Scratch (device globals: allocation-free). Layout [b*H+h][t][64] contiguous.
__device__ float g_Q  [CB*CH*CT*CD];
__device__ float g_V  [CB*CH*CT*CD];
__device__ float g_NW [CB*CH*CT*CD];
__device__ float g_ATT[CB*CH*CT*CD];

// ---------------------------------------------------------------------------
// Per-head 64x64 projection: Y[t,e] = sum_d X[t,d] * W[h,d,e]
// ---------------------------------------------------------------------------
__global__ __launch_bounds__(256) void proj64_kernel(
    const float* __restrict__ X, const float* __restrict__ W,
    float* __restrict__ Y, int x_rs, int y_rs, int x_bte, int y_bte)
{
    __shared__ float Xs[64 * 68];   // transposed [d][t], padded
    __shared__ float Ws[64 * 64];   // [d][e]
    const int bh = blockIdx.y;
    const int b = bh >> 4, h = bh & 15;
    const int t0 = blockIdx.x << 6;
    const float* Xp = X + (x_bte ? ((size_t)b * CT * CE + h * 64)
                                 : ((size_t)bh * CT * 64)) + (size_t)t0 * x_rs;
    float* Yp = Y + (y_bte ? ((size_t)b * CT * CE + h * 64)
                           : ((size_t)bh * CT * 64)) + (size_t)t0 * y_rs;
    const float* Wp = W + h * 4096;
    const int tid = threadIdx.x;

    const float4* W4 = (const float4*)Wp;
    float4* Ws4 = (float4*)Ws;
#pragma unroll
    for (int k = 0; k < 4; k++) Ws4[tid + k * 256] = W4[tid + k * 256];
#pragma unroll
    for (int k = 0; k < 4; k++) {
        int i = tid + k * 256;
        int r = i >> 4, d4 = i & 15;
        float4 v = *(const float4*)(Xp + (size_t)r * x_rs + d4 * 4);
        Xs[(d4 * 4 + 0) * 68 + r] = v.x;
        Xs[(d4 * 4 + 1) * 68 + r] = v.y;
        Xs[(d4 * 4 + 2) * 68 + r] = v.z;
        Xs[(d4 * 4 + 3) * 68 + r] = v.w;
    }
    __syncthreads();

    const int ty = tid >> 4, tx = tid & 15;
    float acc[4][4];
#pragma unroll
    for (int i = 0; i < 4; i++)
#pragma unroll
        for (int j = 0; j < 4; j++) acc[i][j] = 0.f;

#pragma unroll 8
    for (int d = 0; d < 64; d++) {
        float4 a4 = *(const float4*)&Xs[d * 68 + ty * 4];
        float4 w4 = *(const float4*)&Ws[d * 64 + tx * 4];
        float a[4] = {a4.x, a4.y, a4.z, a4.w};
        float w[4] = {w4.x, w4.y, w4.z, w4.w};
#pragma unroll
        for (int i = 0; i < 4; i++)
#pragma unroll
            for (int j = 0; j < 4; j++) acc[i][j] += a[i] * w[j];
    }
#pragma unroll
    for (int i = 0; i < 4; i++) {
        float4 r = make_float4(acc[i][0], acc[i][1], acc[i][2], acc[i][3]);
        *(float4*)(Yp + (size_t)(ty * 4 + i) * y_rs + tx * 4) = r;
    }
}

// ---------------------------------------------------------------------------
// RNN: one block per (b,h) chain. (unchanged from round 2)
// ---------------------------------------------------------------------------
__global__ __launch_bounds__(64) void rnn_kernel(
    const float* __restrict__ target,
    const float* __restrict__ W_ih, const float* __restrict__ W_hh,
    const float* __restrict__ b_ih, const float* __restrict__ b_hh,
    float* __restrict__ NW)
{
    const int bh = blockIdx.x;
    const int b = bh >> 4, h = bh & 15;
    const int e = threadIdx.x;
    __shared__ float hs[2][64];

    float w[64];
    const float* wih = W_ih + h * 4096 + e * 64;
#pragma unroll
    for (int j = 0; j < 64; j++) w[j] = wih[j];
    const float bsum = b_ih[h * 64 + e] + b_hh[h * 64 + e];

    hs[0][e] = target[(size_t)b * CT * CE + h * 64 + e];
    __syncthreads();

    float a0 = bsum, a1 = 0.f, a2 = 0.f, a3 = 0.f;
#pragma unroll
    for (int j = 0; j < 16; j++) {
        float4 hv = *(const float4*)&hs[0][j * 4];
        a0 += hv.x * w[j * 4 + 0];
        a1 += hv.y * w[j * 4 + 1];
        a2 += hv.z * w[j * 4 + 2];
        a3 += hv.w * w[j * 4 + 3];
    }
    float hcur = tanhf((a0 + a1) + (a2 + a3));
    float* nwp = NW + (size_t)bh * CT * 64 + e;
    nwp[0] = hcur;
    hs[1][e] = hcur;

    const float* whh = W_hh + h * 4096 + e * 64;
#pragma unroll
    for (int j = 0; j < 64; j++) w[j] += whh[j];
    __syncthreads();

    int p = 1;
    for (int t = 1; t < CT; t++) {
        float b0 = bsum, b1 = 0.f, b2 = 0.f, b3 = 0.f;
#pragma unroll
        for (int j = 0; j < 16; j++) {
            float4 hv = *(const float4*)&hs[p][j * 4];
            b0 += hv.x * w[j * 4 + 0];
            b1 += hv.y * w[j * 4 + 1];
            b2 += hv.z * w[j * 4 + 2];
            b3 += hv.w * w[j * 4 + 3];
        }
        float hn = tanhf((b0 + b1) + (b2 + b3));
        nwp[(size_t)t * 64] = hn;
        hs[p ^ 1][e] = hn;
        __syncthreads();
        p ^= 1;
    }
}

// ---------------------------------------------------------------------------
// Flash attention on tensor cores: mma.sync.m16n8k8.tf32.
// Block = (b,h, 128-row q-tile), 8 warps, each warp owns 16 q-rows.
// Bk=64 key tiles streamed with online softmax.
// Smem stride 68: fragment pattern addr = 4*group + tig (mod 32) -> conflict-free.
// ---------------------------------------------------------------------------
#define AST 68

__device__ __forceinline__ unsigned f2tf32(float x) {
    unsigned r;
    asm("cvt.rna.tf32.f32 %0, %1;" : "=r"(r) : "f"(x));
    return r;
}

__device__ __forceinline__ void mma_tf32(float* d,
    unsigned a0, unsigned a1, unsigned a2, unsigned a3,
    unsigned b0, unsigned b1)
{
    asm volatile(
        "mma.sync.aligned.m16n8k8.row.col.f32.tf32.tf32.f32 "
        "{%0,%1,%2,%3}, {%4,%5,%6,%7}, {%8,%9}, {%0,%1,%2,%3};"
        : "+f"(d[0]), "+f"(d[1]), "+f"(d[2]), "+f"(d[3])
        : "r"(a0), "r"(a1), "r"(a2), "r"(a3), "r"(b0), "r"(b1));
}

__global__ __launch_bounds__(256) void attn_mma_kernel(
    const float* __restrict__ Q, const float* __restrict__ K,
    const float* __restrict__ V, float* __restrict__ O)
{
    extern __shared__ unsigned sm[];
    unsigned* Ks = sm;                       // 64 x 68 (tf32 bits)
    unsigned* Vs = sm + 64 * AST;            // 64 x 68
    unsigned* Pw = sm + 2 * 64 * AST;        // 8 warps x 16 x 68

    const int bh = blockIdx.y;
    const int q0 = blockIdx.x << 7;          // 128-row q tile
    const int tid = threadIdx.x;
    const int wid = tid >> 5, lane = tid & 31;
    const int g = lane >> 2, c = lane & 3;   // groupID, threadID_in_group
    const int m0 = wid * 16;

    const float* Qp = Q + ((size_t)bh * CT + q0) * 64;
    const float* Kp = K + (size_t)bh * CT * 64;
    const float* Vp = V + (size_t)bh * CT * 64;
    float* Op = O + ((size_t)bh * CT + q0) * 64;

    // ---- stage Q tile (128x64) into smem, then to persistent tf32 A-frags ----
    {
        float* Qstage = (float*)sm;          // 128 x 68 = 8704 floats (fits Ks+Vs)
#pragma unroll
        for (int k = 0; k < 8; k++) {
            int i = tid + k * 256;
            int r = i >> 4, c4 = i & 15;
            float4 v = *(const float4*)(Qp + r * 64 + c4 * 4);
            *(float4*)&Qstage[r * AST + c4 * 4] = v;
        }
        __syncthreads();
    }
    unsigned qa[8][4];
    {
        const float* Qstage = (const float*)sm;
        const float qscale = 1.0f / 256.0f;  // 1/(sqrt(D)*sqrt(T)) folded into Q
#pragma unroll
        for (int kc = 0; kc < 8; kc++) {
            qa[kc][0] = f2tf32(Qstage[(m0 + g)     * AST + kc * 8 + c]     * qscale);
            qa[kc][1] = f2tf32(Qstage[(m0 + g + 8) * AST + kc * 8 + c]     * qscale);
            qa[kc][2] = f2tf32(Qstage[(m0 + g)     * AST + kc * 8 + c + 4] * qscale);
            qa[kc][3] = f2tf32(Qstage[(m0 + g + 8) * AST + kc * 8 + c + 4] * qscale);
        }
    }
    __syncthreads();

    float oacc[8][4];
#pragma unroll
    for (int nb = 0; nb < 8; nb++)
#pragma unroll
        for (int k = 0; k < 4; k++) oacc[nb][k] = 0.f;
    float m0r = -1e30f, m1r = -1e30f, l0 = 0.f, l1 = 0.f;

    unsigned* Pme = Pw + wid * 16 * AST;

    for (int kt = 0; kt < 16; kt++) {
        const float* Kt = Kp + kt * 64 * 64;
        const float* Vt = Vp + kt * 64 * 64;
        // ---- load K/V tiles, convert to tf32 bits in smem ----
#pragma unroll
        for (int k = 0; k < 4; k++) {
            int i = tid + k * 256;
            int r = i >> 4, c4 = i & 15;
            float4 kv = *(const float4*)(Kt + r * 64 + c4 * 4);
            Ks[r * AST + c4 * 4 + 0] = f2tf32(kv.x);
            Ks[r * AST + c4 * 4 + 1] = f2tf32(kv.y);
            Ks[r * AST + c4 * 4 + 2] = f2tf32(kv.z);
            Ks[r * AST + c4 * 4 + 3] = f2tf32(kv.w);
            float4 vv = *(const float4*)(Vt + r * 64 + c4 * 4);
            Vs[r * AST + c4 * 4 + 0] = f2tf32(vv.x);
            Vs[r * AST + c4 * 4 + 1] = f2tf32(vv.y);
            Vs[r * AST + c4 * 4 + 2] = f2tf32(vv.z);
            Vs[r * AST + c4 * 4 + 3] = f2tf32(vv.w);
        }
        __syncthreads();

        // ---- S = (Q*scale) @ K^T : 16x64 per warp ----
        float sacc[8][4];
#pragma unroll
        for (int nb = 0; nb < 8; nb++)
#pragma unroll
            for (int k = 0; k < 4; k++) sacc[nb][k] = 0.f;
#pragma unroll
        for (int kc = 0; kc < 8; kc++) {
#pragma unroll
            for (int nb = 0; nb < 8; nb++) {
                unsigned b0 = Ks[(nb * 8 + g) * AST + kc * 8 + c];
                unsigned b1 = Ks[(nb * 8 + g) * AST + kc * 8 + c + 4];
                mma_tf32(sacc[nb], qa[kc][0], qa[kc][1], qa[kc][2], qa[kc][3], b0, b1);
            }
        }

        // ---- online softmax: thread owns rows (m0+g) [regs 0,1] & (m0+g+8) [2,3] ----
        float mx0 = -1e30f, mx1 = -1e30f;
#pragma unroll
        for (int nb = 0; nb < 8; nb++) {
            mx0 = fmaxf(mx0, fmaxf(sacc[nb][0], sacc[nb][1]));
            mx1 = fmaxf(mx1, fmaxf(sacc[nb][2], sacc[nb][3]));
        }
        mx0 = fmaxf(mx0, __shfl_xor_sync(0xffffffffu, mx0, 1));
        mx0 = fmaxf(mx0, __shfl_xor_sync(0xffffffffu, mx0, 2));
        mx1 = fmaxf(mx1, __shfl_xor_sync(0xffffffffu, mx1, 1));
        mx1 = fmaxf(mx1, __shfl_xor_sync(0xffffffffu, mx1, 2));
        float mn0 = fmaxf(m0r, mx0), mn1 = fmaxf(m1r, mx1);
        float corr0 = __expf(m0r - mn0), corr1 = __expf(m1r - mn1);
        m0r = mn0; m1r = mn1;
        float s0 = 0.f, s1 = 0.f;
#pragma unroll
        for (int nb = 0; nb < 8; nb++) {
            sacc[nb][0] = __expf(sacc[nb][0] - mn0); s0 += sacc[nb][0];
            sacc[nb][1] = __expf(sacc[nb][1] - mn0); s0 += sacc[nb][1];
            sacc[nb][2] = __expf(sacc[nb][2] - mn1); s1 += sacc[nb][2];
            sacc[nb][3] = __expf(sacc[nb][3] - mn1); s1 += sacc[nb][3];
        }
        s0 += __shfl_xor_sync(0xffffffffu, s0, 1);
        s0 += __shfl_xor_sync(0xffffffffu, s0, 2);
        s1 += __shfl_xor_sync(0xffffffffu, s1, 1);
        s1 += __shfl_xor_sync(0xffffffffu, s1, 2);
        l0 = l0 * corr0 + s0;
        l1 = l1 * corr1 + s1;
#pragma unroll
        for (int nb = 0; nb < 8; nb++) {
            oacc[nb][0] *= corr0; oacc[nb][1] *= corr0;
            oacc[nb][2] *= corr1; oacc[nb][3] *= corr1;
        }

        // ---- P -> per-warp smem (C-frag -> A-frag layout change) ----
#pragma unroll
        for (int nb = 0; nb < 8; nb++) {
            uint2 p01 = make_uint2(f2tf32(sacc[nb][0]), f2tf32(sacc[nb][1]));
            uint2 p23 = make_uint2(f2tf32(sacc[nb][2]), f2tf32(sacc[nb][3]));
            *(uint2*)&Pme[g * AST + nb * 8 + 2 * c] = p01;
            *(uint2*)&Pme[(g + 8) * AST + nb * 8 + 2 * c] = p23;
        }
        __syncwarp();

        // ---- O += P @ V ----
#pragma unroll
        for (int jc = 0; jc < 8; jc++) {
            unsigned pa0 = Pme[(g)     * AST + jc * 8 + c];
            unsigned pa1 = Pme[(g + 8) * AST + jc * 8 + c];
            unsigned pa2 = Pme[(g)     * AST + jc * 8 + c + 4];
            unsigned pa3 = Pme[(g + 8) * AST + jc * 8 + c + 4];
#pragma unroll
            for (int nb = 0; nb < 8; nb++) {
                unsigned vb0 = Vs[(jc * 8 + c)     * AST + nb * 8 + g];
                unsigned vb1 = Vs[(jc * 8 + c + 4) * AST + nb * 8 + g];
                mma_tf32(oacc[nb], pa0, pa1, pa2, pa3, vb0, vb1);
            }
        }
        __syncthreads();
    }

    // ---- epilogue ----
    float inv0 = 1.0f / l0, inv1 = 1.0f / l1;
#pragma unroll
    for (int nb = 0; nb < 8; nb++) {
        *(float2*)(Op + (size_t)(m0 + g) * 64 + nb * 8 + 2 * c) =
            make_float2(oacc[nb][0] * inv0, oacc[nb][1] * inv0);
        *(float2*)(Op + (size_t)(m0 + g + 8) * 64 + nb * 8 + 2 * c) =
            make_float2(oacc[nb][2] * inv1, oacc[nb][3] * inv1);
    }
}

// ---------------------------------------------------------------------------
extern "C" void kernel_launch(void* const* d_in, const int* in_sizes, int n_in,
                              void* d_out, int out_size)
{
    (void)in_sizes; (void)n_in; (void)out_size;
    const float* source = (const float*)d_in[0];
    const float* target = (const float*)d_in[1];
    const float* W_q    = (const float*)d_in[2];
    const float* W_v    = (const float*)d_in[3];
    const float* W_o    = (const float*)d_in[4];
    const float* W_ih   = (const float*)d_in[5];
    const float* W_hh   = (const float*)d_in[6];
    const float* b_ih   = (const float*)d_in[7];
    const float* b_hh   = (const float*)d_in[8];
    float* out = (float*)d_out;

    void *pQ, *pV, *pNW, *pATT;
    cudaGetSymbolAddress(&pQ,  g_Q);
    cudaGetSymbolAddress(&pV,  g_V);
    cudaGetSymbolAddress(&pNW, g_NW);
    cudaGetSymbolAddress(&pATT, g_ATT);
    float* Qb   = (float*)pQ;
    float* Vb   = (float*)pV;
    float* NWb  = (float*)pNW;
    float* ATTb = (float*)pATT;

    const dim3 pgrid(CT / 64, CB * CH);

    proj64_kernel<<<pgrid, 256>>>(source, W_q, Qb, CE, 64, 1, 0);
    proj64_kernel<<<pgrid, 256>>>(target, W_v, Vb, CE, 64, 1, 0);

    rnn_kernel<<<CB * CH, 64>>>(target, W_ih, W_hh, b_ih, b_hh, NWb);

    // Flash attention on tensor cores
    const int attn_smem = (2 * 64 * AST + 8 * 16 * AST) * (int)sizeof(unsigned); // 69632 B
    cudaFuncSetAttribute(attn_mma_kernel,
                         cudaFuncAttributeMaxDynamicSharedMemorySize, attn_smem);
    const dim3 agrid(CT / 128, CB * CH);
    attn_mma_kernel<<<agrid, 256, attn_smem>>>(Qb, NWb, Vb, ATTb);

    proj64_kernel<<<pgrid, 256>>>(ATTb, W_o, out, 64, CE, 0, 1);
}

// round 10
// speedup vs baseline: 2.2930x; 1.1117x over previous
#include <cuda_runtime.h>
#include <math.h>

#define CB 8
#define CT 1024
#define CE 1024
#define CH 16
#define CD 64

// Scratch (device globals). Layout [b*H+h][t][64] contiguous.
__device__ float g_Q  [CB*CH*CT*CD];
__device__ float g_V  [CB*CH*CT*CD];
__device__ float g_NW [CB*CH*CT*CD];
__device__ float g_ATT[CB*CH*CT*CD];

// ---------------------------------------------------------------------------
// tf32 mma helpers (same fragment mapping as the round-3 kernel that passed)
// ---------------------------------------------------------------------------
__device__ __forceinline__ unsigned f2tf32(float x) {
    unsigned r;
    asm("cvt.rna.tf32.f32 %0, %1;" : "=r"(r) : "f"(x));
    return r;
}
__device__ __forceinline__ void mma_tf32(float* d,
    unsigned a0, unsigned a1, unsigned a2, unsigned a3,
    unsigned b0, unsigned b1)
{
    asm volatile(
        "mma.sync.aligned.m16n8k8.row.col.f32.tf32.tf32.f32 "
        "{%0,%1,%2,%3}, {%4,%5,%6,%7}, {%8,%9}, {%0,%1,%2,%3};"
        : "+f"(d[0]), "+f"(d[1]), "+f"(d[2]), "+f"(d[3])
        : "r"(a0), "r"(a1), "r"(a2), "r"(a3), "r"(b0), "r"(b1));
}

// ---------------------------------------------------------------------------
// Projection on tensor cores: Y[128,64] tile = X[128,64] @ W[64,64], per (b,h).
// 128 threads / 4 warps; warp owns 32 rows as two 16-row mma halves.
// ---------------------------------------------------------------------------
__global__ __launch_bounds__(128) void proj_mma_kernel(
    const float* __restrict__ X, const float* __restrict__ W,
    float* __restrict__ Y, int x_rs, int y_rs, int x_bte, int y_bte)
{
    extern __shared__ unsigned psm[];
    float*    Xs = (float*)psm;            // 128 x 68 raw floats
    unsigned* Ws = psm + 128 * 68;         // 64 x 68 tf32 bits

    const int bh = blockIdx.y;
    const int b = bh >> 4, h = bh & 15;
    const int t0 = blockIdx.x << 7;        // 128-row tile
    const float* Xp = X + (x_bte ? ((size_t)b * CT * CE + h * 64)
                                 : ((size_t)bh * CT * 64)) + (size_t)t0 * x_rs;
    float* Yp = Y + (y_bte ? ((size_t)b * CT * CE + h * 64)
                           : ((size_t)bh * CT * 64)) + (size_t)t0 * y_rs;
    const float* Wp = W + h * 4096;
    const int tid = threadIdx.x;
    const int wid = tid >> 5, lane = tid & 31;
    const int g = lane >> 2, c = lane & 3;
    const int m0 = wid * 32;

    // stage X (raw): 128 rows x 64 cols = 2048 float4 -> k < 16 with 128 thr
#pragma unroll
    for (int k = 0; k < 16; k++) {
        int i = tid + k * 128;
        int r = i >> 4, c4 = i & 15;
        float4 v = *(const float4*)(Xp + (size_t)r * x_rs + c4 * 4);
        *(float4*)&Xs[r * 68 + c4 * 4] = v;
    }
    // stage W (tf32): 64 x 64 = 1024 float4 -> k < 8
#pragma unroll
    for (int k = 0; k < 8; k++) {
        int i = tid + k * 128;
        int d = i >> 4, c4 = i & 15;
        float4 v = *(const float4*)(Wp + d * 64 + c4 * 4);
        uint4 u = make_uint4(f2tf32(v.x), f2tf32(v.y), f2tf32(v.z), f2tf32(v.w));
        *(uint4*)&Ws[d * 68 + c4 * 4] = u;
    }
    __syncthreads();

    float acc0[8][4], acc1[8][4];
#pragma unroll
    for (int nb = 0; nb < 8; nb++)
#pragma unroll
        for (int k = 0; k < 4; k++) { acc0[nb][k] = 0.f; acc1[nb][k] = 0.f; }

#pragma unroll
    for (int kc = 0; kc < 8; kc++) {
        unsigned a0 = f2tf32(Xs[(m0 + g)      * 68 + kc * 8 + c]);
        unsigned a1 = f2tf32(Xs[(m0 + g + 8)  * 68 + kc * 8 + c]);
        unsigned a2 = f2tf32(Xs[(m0 + g)      * 68 + kc * 8 + c + 4]);
        unsigned a3 = f2tf32(Xs[(m0 + g + 8)  * 68 + kc * 8 + c + 4]);
        unsigned e0 = f2tf32(Xs[(m0 + g + 16) * 68 + kc * 8 + c]);
        unsigned e1 = f2tf32(Xs[(m0 + g + 24) * 68 + kc * 8 + c]);
        unsigned e2 = f2tf32(Xs[(m0 + g + 16) * 68 + kc * 8 + c + 4]);
        unsigned e3 = f2tf32(Xs[(m0 + g + 24) * 68 + kc * 8 + c + 4]);
#pragma unroll
        for (int nb = 0; nb < 8; nb++) {
            unsigned b0 = Ws[(kc * 8 + c)     * 68 + nb * 8 + g];
            unsigned b1 = Ws[(kc * 8 + c + 4) * 68 + nb * 8 + g];
            mma_tf32(acc0[nb], a0, a1, a2, a3, b0, b1);
            mma_tf32(acc1[nb], e0, e1, e2, e3, b0, b1);
        }
    }
#pragma unroll
    for (int nb = 0; nb < 8; nb++) {
        *(float2*)(Yp + (size_t)(m0 + g)      * y_rs + nb * 8 + 2 * c) = make_float2(acc0[nb][0], acc0[nb][1]);
        *(float2*)(Yp + (size_t)(m0 + g + 8)  * y_rs + nb * 8 + 2 * c) = make_float2(acc0[nb][2], acc0[nb][3]);
        *(float2*)(Yp + (size_t)(m0 + g + 16) * y_rs + nb * 8 + 2 * c) = make_float2(acc1[nb][0], acc1[nb][1]);
        *(float2*)(Yp + (size_t)(m0 + g + 24) * y_rs + nb * 8 + 2 * c) = make_float2(acc1[nb][2], acc1[nb][3]);
    }
}

// ---------------------------------------------------------------------------
// RNN: one block per (b,h) chain. 128 threads: pair (2e, 2e+1) splits the
// 64-term dot; shfl_xor(1) combines (pairs are in-warp). Fast tanh via expf.
// ---------------------------------------------------------------------------
__device__ __forceinline__ float tanh_fast(float x) {
    float e = __expf(2.f * x);
    return 1.f - __fdividef(2.f, e + 1.f);
}

__global__ __launch_bounds__(128) void rnn_kernel(
    const float* __restrict__ target,
    const float* __restrict__ W_ih, const float* __restrict__ W_hh,
    const float* __restrict__ b_ih, const float* __restrict__ b_hh,
    float* __restrict__ NW)
{
    const int bh = blockIdx.x;
    const int b = bh >> 4, h = bh & 15;
    const int tid = threadIdx.x;
    const int e = tid >> 1, half = tid & 1;
    __shared__ float hs[2][64];

    float w[32];
    const float* wih = W_ih + h * 4096 + e * 64 + half * 32;
#pragma unroll
    for (int j = 0; j < 32; j++) w[j] = wih[j];
    const float bsum = b_ih[h * 64 + e] + b_hh[h * 64 + e];

    if (half == 0)
        hs[0][e] = target[(size_t)b * CT * CE + h * 64 + e];
    __syncthreads();

    // step 1: W_ih only
    {
        float a0 = 0.f, a1 = 0.f, a2 = 0.f, a3 = 0.f;
        const float* hb = &hs[0][half * 32];
#pragma unroll
        for (int j = 0; j < 8; j++) {
            float4 hv = *(const float4*)&hb[j * 4];
            a0 += hv.x * w[j * 4 + 0];
            a1 += hv.y * w[j * 4 + 1];
            a2 += hv.z * w[j * 4 + 2];
            a3 += hv.w * w[j * 4 + 3];
        }
        float part = (a0 + a1) + (a2 + a3);
        part += __shfl_xor_sync(0xffffffffu, part, 1);
        float hcur = tanh_fast(part + bsum);
        if (half == 0) {
            NW[(size_t)bh * CT * 64 + e] = hcur;
            hs[1][e] = hcur;
        }
    }
    const float* whh = W_hh + h * 4096 + e * 64 + half * 32;
#pragma unroll
    for (int j = 0; j < 32; j++) w[j] += whh[j];   // W_sum for steps >= 2
    __syncthreads();

    float* nwp = NW + (size_t)bh * CT * 64 + e;
    int p = 1;
    for (int t = 1; t < CT; t++) {
        float a0 = 0.f, a1 = 0.f, a2 = 0.f, a3 = 0.f;
        const float* hb = &hs[p][half * 32];
#pragma unroll
        for (int j = 0; j < 8; j++) {
            float4 hv = *(const float4*)&hb[j * 4];
            a0 += hv.x * w[j * 4 + 0];
            a1 += hv.y * w[j * 4 + 1];
            a2 += hv.z * w[j * 4 + 2];
            a3 += hv.w * w[j * 4 + 3];
        }
        float part = (a0 + a1) + (a2 + a3);
        part += __shfl_xor_sync(0xffffffffu, part, 1);
        float hn = tanh_fast(part + bsum);
        if (half == 0) {
            nwp[(size_t)t * 64] = hn;
            hs[p ^ 1][e] = hn;
        }
        __syncthreads();
        p ^= 1;
    }
}

// ---------------------------------------------------------------------------
// Flash attention, tf32 mma, 32 q-rows per warp (two 16-row halves live so
// every K/V B-fragment LDS feeds two mma's). 128 threads / 4 warps / 128 q.
// Smem: Ks,Vs 64x68 tf32; Qpk packed half1 A-frags; Pw 4x(32x68) P strips
// (Q staging tile aliases Pw).
// ---------------------------------------------------------------------------
#define AST 68
#define SM_KS 0
#define SM_VS (64 * AST)
#define SM_QPK (2 * 64 * AST)
#define SM_PW (2 * 64 * AST + 4096)
#define SM_ATTN_WORDS (SM_PW + 4 * 32 * AST)

__global__ __launch_bounds__(128) void attn_mma_kernel(
    const float* __restrict__ Q, const float* __restrict__ K,
    const float* __restrict__ V, float* __restrict__ O)
{
    extern __shared__ unsigned sm[];
    unsigned* Ks  = sm + SM_KS;
    unsigned* Vs  = sm + SM_VS;
    unsigned* Qpk = sm + SM_QPK;
    unsigned* Pw  = sm + SM_PW;

    const int bh = blockIdx.y;
    const int q0 = blockIdx.x << 7;          // 128-row q tile
    const int tid = threadIdx.x;
    const int wid = tid >> 5, lane = tid & 31;
    const int g = lane >> 2, c = lane & 3;
    const int m0 = wid * 32;

    const float* Qp = Q + ((size_t)bh * CT + q0) * 64;
    const float* Kp = K + (size_t)bh * CT * 64;
    const float* Vp = V + (size_t)bh * CT * 64;
    float* Op = O + ((size_t)bh * CT + q0) * 64;

    // ---- stage FULL 128-row Q tile into Pw region (2048 float4 -> k < 16)
    {
        float* Qstage = (float*)Pw;          // 128 x 68
#pragma unroll
        for (int k = 0; k < 16; k++) {
            int i = tid + k * 128;
            int r = i >> 4, c4 = i & 15;
            float4 v = *(const float4*)(Qp + r * 64 + c4 * 4);
            *(float4*)&Qstage[r * AST + c4 * 4] = v;
        }
        __syncthreads();
    }
    // ---- build A-frags: half0 (rows m0..m0+15) in regs, half1 packed to smem
    unsigned qa[8][4];
    {
        const float* Qstage = (const float*)Pw;
        const float qscale = 1.0f / 256.0f;  // 1/(sqrt(D)*sqrt(T))
#pragma unroll
        for (int kc = 0; kc < 8; kc++) {
            qa[kc][0] = f2tf32(Qstage[(m0 + g)     * AST + kc * 8 + c]     * qscale);
            qa[kc][1] = f2tf32(Qstage[(m0 + g + 8) * AST + kc * 8 + c]     * qscale);
            qa[kc][2] = f2tf32(Qstage[(m0 + g)     * AST + kc * 8 + c + 4] * qscale);
            qa[kc][3] = f2tf32(Qstage[(m0 + g + 8) * AST + kc * 8 + c + 4] * qscale);
            uint4 qb;
            qb.x = f2tf32(Qstage[(m0 + g + 16) * AST + kc * 8 + c]     * qscale);
            qb.y = f2tf32(Qstage[(m0 + g + 24) * AST + kc * 8 + c]     * qscale);
            qb.z = f2tf32(Qstage[(m0 + g + 16) * AST + kc * 8 + c + 4] * qscale);
            qb.w = f2tf32(Qstage[(m0 + g + 24) * AST + kc * 8 + c + 4] * qscale);
            *(uint4*)&Qpk[((wid * 8 + kc) * 32 + lane) * 4] = qb;   // Qpk != Qstage
        }
    }
    __syncthreads();   // Qstage reads done before Pw strips are overwritten

    float oacc0[8][4], oacc1[8][4];
#pragma unroll
    for (int nb = 0; nb < 8; nb++)
#pragma unroll
        for (int k = 0; k < 4; k++) { oacc0[nb][k] = 0.f; oacc1[nb][k] = 0.f; }
    float m00 = -1e30f, m01 = -1e30f, m10 = -1e30f, m11 = -1e30f;
    float l00 = 0.f, l01 = 0.f, l10 = 0.f, l11 = 0.f;

    unsigned* Pme = Pw + wid * 32 * AST;

    for (int kt = 0; kt < 16; kt++) {
        const float* Kt = Kp + kt * 64 * 64;
        const float* Vt = Vp + kt * 64 * 64;
#pragma unroll
        for (int k = 0; k < 8; k++) {
            int i = tid + k * 128;
            int r = i >> 4, c4 = i & 15;
            float4 kv = *(const float4*)(Kt + r * 64 + c4 * 4);
            *(uint4*)&Ks[r * AST + c4 * 4] =
                make_uint4(f2tf32(kv.x), f2tf32(kv.y), f2tf32(kv.z), f2tf32(kv.w));
            float4 vv = *(const float4*)(Vt + r * 64 + c4 * 4);
            *(uint4*)&Vs[r * AST + c4 * 4] =
                make_uint4(f2tf32(vv.x), f2tf32(vv.y), f2tf32(vv.z), f2tf32(vv.w));
        }
        __syncthreads();

        // ---- S = Q @ K^T : 32x64 per warp; B-frags reused by both halves ----
        float s0[8][4], s1[8][4];
#pragma unroll
        for (int nb = 0; nb < 8; nb++)
#pragma unroll
            for (int k = 0; k < 4; k++) { s0[nb][k] = 0.f; s1[nb][k] = 0.f; }
#pragma unroll
        for (int kc = 0; kc < 8; kc++) {
            uint4 qb = *(const uint4*)&Qpk[((wid * 8 + kc) * 32 + lane) * 4];
#pragma unroll
            for (int nb = 0; nb < 8; nb++) {
                unsigned b0 = Ks[(nb * 8 + g) * AST + kc * 8 + c];
                unsigned b1 = Ks[(nb * 8 + g) * AST + kc * 8 + c + 4];
                mma_tf32(s0[nb], qa[kc][0], qa[kc][1], qa[kc][2], qa[kc][3], b0, b1);
                mma_tf32(s1[nb], qb.x, qb.y, qb.z, qb.w, b0, b1);
            }
        }

        // ---- online softmax (4 row-sets per thread) ----
        float x00 = -1e30f, x01 = -1e30f, x10 = -1e30f, x11 = -1e30f;
#pragma unroll
        for (int nb = 0; nb < 8; nb++) {
            x00 = fmaxf(x00, fmaxf(s0[nb][0], s0[nb][1]));
            x01 = fmaxf(x01, fmaxf(s0[nb][2], s0[nb][3]));
            x10 = fmaxf(x10, fmaxf(s1[nb][0], s1[nb][1]));
            x11 = fmaxf(x11, fmaxf(s1[nb][2], s1[nb][3]));
        }
#pragma unroll
        for (int off = 1; off <= 2; off <<= 1) {
            x00 = fmaxf(x00, __shfl_xor_sync(0xffffffffu, x00, off));
            x01 = fmaxf(x01, __shfl_xor_sync(0xffffffffu, x01, off));
            x10 = fmaxf(x10, __shfl_xor_sync(0xffffffffu, x10, off));
            x11 = fmaxf(x11, __shfl_xor_sync(0xffffffffu, x11, off));
        }
        float n00 = fmaxf(m00, x00), n01 = fmaxf(m01, x01);
        float n10 = fmaxf(m10, x10), n11 = fmaxf(m11, x11);
        float c00 = __expf(m00 - n00), c01 = __expf(m01 - n01);
        float c10 = __expf(m10 - n10), c11 = __expf(m11 - n11);
        m00 = n00; m01 = n01; m10 = n10; m11 = n11;
        float r00 = 0.f, r01 = 0.f, r10 = 0.f, r11 = 0.f;
#pragma unroll
        for (int nb = 0; nb < 8; nb++) {
            s0[nb][0] = __expf(s0[nb][0] - n00); r00 += s0[nb][0];
            s0[nb][1] = __expf(s0[nb][1] - n00); r00 += s0[nb][1];
            s0[nb][2] = __expf(s0[nb][2] - n01); r01 += s0[nb][2];
            s0[nb][3] = __expf(s0[nb][3] - n01); r01 += s0[nb][3];
            s1[nb][0] = __expf(s1[nb][0] - n10); r10 += s1[nb][0];
            s1[nb][1] = __expf(s1[nb][1] - n10); r10 += s1[nb][1];
            s1[nb][2] = __expf(s1[nb][2] - n11); r11 += s1[nb][2];
            s1[nb][3] = __expf(s1[nb][3] - n11); r11 += s1[nb][3];
        }
#pragma unroll
        for (int off = 1; off <= 2; off <<= 1) {
            r00 += __shfl_xor_sync(0xffffffffu, r00, off);
            r01 += __shfl_xor_sync(0xffffffffu, r01, off);
            r10 += __shfl_xor_sync(0xffffffffu, r10, off);
            r11 += __shfl_xor_sync(0xffffffffu, r11, off);
        }
        l00 = l00 * c00 + r00; l01 = l01 * c01 + r01;
        l10 = l10 * c10 + r10; l11 = l11 * c11 + r11;
#pragma unroll
        for (int nb = 0; nb < 8; nb++) {
            oacc0[nb][0] *= c00; oacc0[nb][1] *= c00;
            oacc0[nb][2] *= c01; oacc0[nb][3] *= c01;
            oacc1[nb][0] *= c10; oacc1[nb][1] *= c10;
            oacc1[nb][2] *= c11; oacc1[nb][3] *= c11;
        }

        // ---- P -> per-warp strip (rows 0..15 half0, 16..31 half1) ----
#pragma unroll
        for (int nb = 0; nb < 8; nb++) {
            *(uint2*)&Pme[(g)      * AST + nb * 8 + 2 * c] = make_uint2(f2tf32(s0[nb][0]), f2tf32(s0[nb][1]));
            *(uint2*)&Pme[(g + 8)  * AST + nb * 8 + 2 * c] = make_uint2(f2tf32(s0[nb][2]), f2tf32(s0[nb][3]));
            *(uint2*)&Pme[(g + 16) * AST + nb * 8 + 2 * c] = make_uint2(f2tf32(s1[nb][0]), f2tf32(s1[nb][1]));
            *(uint2*)&Pme[(g + 24) * AST + nb * 8 + 2 * c] = make_uint2(f2tf32(s1[nb][2]), f2tf32(s1[nb][3]));
        }
        __syncwarp();

        // ---- O += P @ V ; V B-frags reused by both halves ----
#pragma unroll
        for (int jc = 0; jc < 8; jc++) {
            unsigned pa0 = Pme[(g)      * AST + jc * 8 + c];
            unsigned pa1 = Pme[(g + 8)  * AST + jc * 8 + c];
            unsigned pa2 = Pme[(g)      * AST + jc * 8 + c + 4];
            unsigned pa3 = Pme[(g + 8)  * AST + jc * 8 + c + 4];
            unsigned pb0 = Pme[(g + 16) * AST + jc * 8 + c];
            unsigned pb1 = Pme[(g + 24) * AST + jc * 8 + c];
            unsigned pb2 = Pme[(g + 16) * AST + jc * 8 + c + 4];
            unsigned pb3 = Pme[(g + 24) * AST + jc * 8 + c + 4];
#pragma unroll
            for (int nb = 0; nb < 8; nb++) {
                unsigned vb0 = Vs[(jc * 8 + c)     * AST + nb * 8 + g];
                unsigned vb1 = Vs[(jc * 8 + c + 4) * AST + nb * 8 + g];
                mma_tf32(oacc0[nb], pa0, pa1, pa2, pa3, vb0, vb1);
                mma_tf32(oacc1[nb], pb0, pb1, pb2, pb3, vb0, vb1);
            }
        }
        __syncthreads();
    }

    // ---- epilogue ----
    float i00 = 1.f / l00, i01 = 1.f / l01, i10 = 1.f / l10, i11 = 1.f / l11;
#pragma unroll
    for (int nb = 0; nb < 8; nb++) {
        *(float2*)(Op + (size_t)(m0 + g)      * 64 + nb * 8 + 2 * c) = make_float2(oacc0[nb][0] * i00, oacc0[nb][1] * i00);
        *(float2*)(Op + (size_t)(m0 + g + 8)  * 64 + nb * 8 + 2 * c) = make_float2(oacc0[nb][2] * i01, oacc0[nb][3] * i01);
        *(float2*)(Op + (size_t)(m0 + g + 16) * 64 + nb * 8 + 2 * c) = make_float2(oacc1[nb][0] * i10, oacc1[nb][1] * i10);
        *(float2*)(Op + (size_t)(m0 + g + 24) * 64 + nb * 8 + 2 * c) = make_float2(oacc1[nb][2] * i11, oacc1[nb][3] * i11);
    }
}

// ---------------------------------------------------------------------------
extern "C" void kernel_launch(void* const* d_in, const int* in_sizes, int n_in,
                              void* d_out, int out_size)
{
    (void)in_sizes; (void)n_in; (void)out_size;
    const float* source = (const float*)d_in[0];
    const float* target = (const float*)d_in[1];
    const float* W_q    = (const float*)d_in[2];
    const float* W_v    = (const float*)d_in[3];
    const float* W_o    = (const float*)d_in[4];
    const float* W_ih   = (const float*)d_in[5];
    const float* W_hh   = (const float*)d_in[6];
    const float* b_ih   = (const float*)d_in[7];
    const float* b_hh   = (const float*)d_in[8];
    float* out = (float*)d_out;

    void *pQ, *pV, *pNW, *pATT;
    cudaGetSymbolAddress(&pQ,  g_Q);
    cudaGetSymbolAddress(&pV,  g_V);
    cudaGetSymbolAddress(&pNW, g_NW);
    cudaGetSymbolAddress(&pATT, g_ATT);
    float* Qb   = (float*)pQ;
    float* Vb   = (float*)pV;
    float* NWb  = (float*)pNW;
    float* ATTb = (float*)pATT;

    const int proj_smem = (128 * 68 + 64 * 68) * (int)sizeof(float);   // 52224
    cudaFuncSetAttribute(proj_mma_kernel,
                         cudaFuncAttributeMaxDynamicSharedMemorySize, proj_smem);
    const int attn_smem = SM_ATTN_WORDS * (int)sizeof(unsigned);       // 86016
    cudaFuncSetAttribute(attn_mma_kernel,
                         cudaFuncAttributeMaxDynamicSharedMemorySize, attn_smem);

    const dim3 pgrid(CT / 128, CB * CH);

    proj_mma_kernel<<<pgrid, 128, proj_smem>>>(source, W_q, Qb, CE, 64, 1, 0);
    proj_mma_kernel<<<pgrid, 128, proj_smem>>>(target, W_v, Vb, CE, 64, 1, 0);

    rnn_kernel<<<CB * CH, 128>>>(target, W_ih, W_hh, b_ih, b_hh, NWb);

    attn_mma_kernel<<<pgrid, 128, attn_smem>>>(Qb, NWb, Vb, ATTb);

    proj_mma_kernel<<<pgrid, 128, proj_smem>>>(ATTb, W_o, out, 64, CE, 0, 1);
}

// round 11
// speedup vs baseline: 2.6441x; 1.1531x over previous
#include <cuda_runtime.h>
#include <math.h>

#define CB 8
#define CT 1024
#define CE 1024
#define CH 16
#define CD 64

// Scratch (device globals). Layout [b*H+h][t][64] contiguous.
__device__ float g_Q  [CB*CH*CT*CD];
__device__ float g_V  [CB*CH*CT*CD];
__device__ float g_NW [CB*CH*CT*CD];
__device__ float g_ATT[CB*CH*CT*CD];

// ---------------------------------------------------------------------------
// tf32 mma helpers
// ---------------------------------------------------------------------------
__device__ __forceinline__ unsigned f2tf32(float x) {
    unsigned r;
    asm("cvt.rna.tf32.f32 %0, %1;" : "=r"(r) : "f"(x));
    return r;
}
__device__ __forceinline__ float rnd_tf32(float x) {
    return __uint_as_float(f2tf32(x));
}
__device__ __forceinline__ float ex2_fast(float x) {
    float y;
    asm("ex2.approx.f32 %0, %1;" : "=f"(y) : "f"(x));
    return y;
}
__device__ __forceinline__ void mma_tf32(float* d,
    unsigned a0, unsigned a1, unsigned a2, unsigned a3,
    unsigned b0, unsigned b1)
{
    asm volatile(
        "mma.sync.aligned.m16n8k8.row.col.f32.tf32.tf32.f32 "
        "{%0,%1,%2,%3}, {%4,%5,%6,%7}, {%8,%9}, {%0,%1,%2,%3};"
        : "+f"(d[0]), "+f"(d[1]), "+f"(d[2]), "+f"(d[3])
        : "r"(a0), "r"(a1), "r"(a2), "r"(a3), "r"(b0), "r"(b1));
}
__device__ __forceinline__ void cp_async16(unsigned saddr, const void* gptr) {
    asm volatile("cp.async.cg.shared.global [%0], [%1], 16;"
                 :: "r"(saddr), "l"(gptr));
}
#define CP_COMMIT() asm volatile("cp.async.commit_group;")
#define CP_WAIT0()  asm volatile("cp.async.wait_group 0;")

// ---------------------------------------------------------------------------
// Projection on tensor cores: Y[128,64] tile = X[128,64] @ W[64,64], per (b,h).
// round_out: round result to tf32 (for V so attention can eat raw bits).
// ---------------------------------------------------------------------------
__global__ __launch_bounds__(128) void proj_mma_kernel(
    const float* __restrict__ X, const float* __restrict__ W,
    float* __restrict__ Y, int x_rs, int y_rs, int x_bte, int y_bte,
    int round_out)
{
    extern __shared__ unsigned psm[];
    float*    Xs = (float*)psm;            // 128 x 68 raw floats
    unsigned* Ws = psm + 128 * 68;         // 64 x 68 tf32 bits

    const int bh = blockIdx.y;
    const int b = bh >> 4, h = bh & 15;
    const int t0 = blockIdx.x << 7;
    const float* Xp = X + (x_bte ? ((size_t)b * CT * CE + h * 64)
                                 : ((size_t)bh * CT * 64)) + (size_t)t0 * x_rs;
    float* Yp = Y + (y_bte ? ((size_t)b * CT * CE + h * 64)
                           : ((size_t)bh * CT * 64)) + (size_t)t0 * y_rs;
    const float* Wp = W + h * 4096;
    const int tid = threadIdx.x;
    const int wid = tid >> 5, lane = tid & 31;
    const int g = lane >> 2, c = lane & 3;
    const int m0 = wid * 32;

#pragma unroll
    for (int k = 0; k < 16; k++) {
        int i = tid + k * 128;
        int r = i >> 4, c4 = i & 15;
        float4 v = *(const float4*)(Xp + (size_t)r * x_rs + c4 * 4);
        *(float4*)&Xs[r * 68 + c4 * 4] = v;
    }
#pragma unroll
    for (int k = 0; k < 8; k++) {
        int i = tid + k * 128;
        int d = i >> 4, c4 = i & 15;
        float4 v = *(const float4*)(Wp + d * 64 + c4 * 4);
        uint4 u = make_uint4(f2tf32(v.x), f2tf32(v.y), f2tf32(v.z), f2tf32(v.w));
        *(uint4*)&Ws[d * 68 + c4 * 4] = u;
    }
    __syncthreads();

    float acc0[8][4], acc1[8][4];
#pragma unroll
    for (int nb = 0; nb < 8; nb++)
#pragma unroll
        for (int k = 0; k < 4; k++) { acc0[nb][k] = 0.f; acc1[nb][k] = 0.f; }

#pragma unroll
    for (int kc = 0; kc < 8; kc++) {
        unsigned a0 = f2tf32(Xs[(m0 + g)      * 68 + kc * 8 + c]);
        unsigned a1 = f2tf32(Xs[(m0 + g + 8)  * 68 + kc * 8 + c]);
        unsigned a2 = f2tf32(Xs[(m0 + g)      * 68 + kc * 8 + c + 4]);
        unsigned a3 = f2tf32(Xs[(m0 + g + 8)  * 68 + kc * 8 + c + 4]);
        unsigned e0 = f2tf32(Xs[(m0 + g + 16) * 68 + kc * 8 + c]);
        unsigned e1 = f2tf32(Xs[(m0 + g + 24) * 68 + kc * 8 + c]);
        unsigned e2 = f2tf32(Xs[(m0 + g + 16) * 68 + kc * 8 + c + 4]);
        unsigned e3 = f2tf32(Xs[(m0 + g + 24) * 68 + kc * 8 + c + 4]);
#pragma unroll
        for (int nb = 0; nb < 8; nb++) {
            unsigned b0 = Ws[(kc * 8 + c)     * 68 + nb * 8 + g];
            unsigned b1 = Ws[(kc * 8 + c + 4) * 68 + nb * 8 + g];
            mma_tf32(acc0[nb], a0, a1, a2, a3, b0, b1);
            mma_tf32(acc1[nb], e0, e1, e2, e3, b0, b1);
        }
    }
    if (round_out) {
#pragma unroll
        for (int nb = 0; nb < 8; nb++)
#pragma unroll
            for (int k = 0; k < 4; k++) {
                acc0[nb][k] = rnd_tf32(acc0[nb][k]);
                acc1[nb][k] = rnd_tf32(acc1[nb][k]);
            }
    }
#pragma unroll
    for (int nb = 0; nb < 8; nb++) {
        *(float2*)(Yp + (size_t)(m0 + g)      * y_rs + nb * 8 + 2 * c) = make_float2(acc0[nb][0], acc0[nb][1]);
        *(float2*)(Yp + (size_t)(m0 + g + 8)  * y_rs + nb * 8 + 2 * c) = make_float2(acc0[nb][2], acc0[nb][3]);
        *(float2*)(Yp + (size_t)(m0 + g + 16) * y_rs + nb * 8 + 2 * c) = make_float2(acc1[nb][0], acc1[nb][1]);
        *(float2*)(Yp + (size_t)(m0 + g + 24) * y_rs + nb * 8 + 2 * c) = make_float2(acc1[nb][2], acc1[nb][3]);
    }
}

// ---------------------------------------------------------------------------
// RNN: one block per (b,h) chain. 128 threads, pair split-K, tanh.approx.
// Stored keys are rounded to tf32 (recurrent state stays full fp32).
// ---------------------------------------------------------------------------
__device__ __forceinline__ float tanh_fast(float x) {
    float y;
    asm("tanh.approx.f32 %0, %1;" : "=f"(y) : "f"(x));
    return y;
}

__global__ __launch_bounds__(128) void rnn_kernel(
    const float* __restrict__ target,
    const float* __restrict__ W_ih, const float* __restrict__ W_hh,
    const float* __restrict__ b_ih, const float* __restrict__ b_hh,
    float* __restrict__ NW)
{
    const int bh = blockIdx.x;
    const int b = bh >> 4, h = bh & 15;
    const int tid = threadIdx.x;
    const int e = tid >> 1, half = tid & 1;
    __shared__ float hs[2][64];

    float w[32];
    const float* wih = W_ih + h * 4096 + e * 64 + half * 32;
#pragma unroll
    for (int j = 0; j < 32; j++) w[j] = wih[j];
    const float bsum = b_ih[h * 64 + e] + b_hh[h * 64 + e];

    if (half == 0)
        hs[0][e] = target[(size_t)b * CT * CE + h * 64 + e];
    __syncthreads();

    // step 1: W_ih only
    {
        float a0 = 0.f, a1 = 0.f, a2 = 0.f, a3 = 0.f;
        const float* hb = &hs[0][half * 32];
#pragma unroll
        for (int j = 0; j < 8; j++) {
            float4 hv = *(const float4*)&hb[j * 4];
            a0 += hv.x * w[j * 4 + 0];
            a1 += hv.y * w[j * 4 + 1];
            a2 += hv.z * w[j * 4 + 2];
            a3 += hv.w * w[j * 4 + 3];
        }
        float part = (a0 + a1) + (a2 + a3);
        part += __shfl_xor_sync(0xffffffffu, part, 1);
        float hcur = tanh_fast(part + bsum);
        if (half == 0) {
            NW[(size_t)bh * CT * 64 + e] = rnd_tf32(hcur);
            hs[1][e] = hcur;
        }
    }
    const float* whh = W_hh + h * 4096 + e * 64 + half * 32;
#pragma unroll
    for (int j = 0; j < 32; j++) w[j] += whh[j];
    __syncthreads();

    float* nwp = NW + (size_t)bh * CT * 64 + e;
    int p = 1;
    for (int t = 1; t < CT; t++) {
        float a0 = 0.f, a1 = 0.f, a2 = 0.f, a3 = 0.f;
        const float* hb = &hs[p][half * 32];
#pragma unroll
        for (int j = 0; j < 8; j++) {
            float4 hv = *(const float4*)&hb[j * 4];
            a0 += hv.x * w[j * 4 + 0];
            a1 += hv.y * w[j * 4 + 1];
            a2 += hv.z * w[j * 4 + 2];
            a3 += hv.w * w[j * 4 + 3];
        }
        float part = (a0 + a1) + (a2 + a3);
        part += __shfl_xor_sync(0xffffffffu, part, 1);
        float hn = tanh_fast(part + bsum);
        if (half == 0) {
            nwp[(size_t)t * 64] = rnd_tf32(hn);
            hs[p ^ 1][e] = hn;
        }
        __syncthreads();
        p ^= 1;
    }
}

// ---------------------------------------------------------------------------
// Flash attention, tf32 mma, cp.async double-buffered K/V (raw tf32-rounded
// bits fed directly to mma), max-free softmax, shfl-based P transpose.
// 128 threads / 4 warps, 128-row q tile, 32 q-rows per warp.
// Smem: [K0][V0][K1][V1] 4 x 64x68 raw + Qpk 4096. Q staged in K1/V1 area.
// ---------------------------------------------------------------------------
#define AST 68
#define TILE_W (64 * AST)                  // 4352 words
#define SM_QPK (4 * TILE_W)                // 17408
#define SM_ATTN_WORDS (SM_QPK + 4096)      // 21504 words = 86016 B

__global__ __launch_bounds__(128, 2) void attn_mma_kernel(
    const float* __restrict__ Q, const float* __restrict__ K,
    const float* __restrict__ V, float* __restrict__ O)
{
    extern __shared__ unsigned sm[];
    unsigned* Qpk = sm + SM_QPK;
    const unsigned sbase = (unsigned)__cvta_generic_to_shared(sm);

    const int bh = blockIdx.y;
    const int q0 = blockIdx.x << 7;
    const int tid = threadIdx.x;
    const int wid = tid >> 5, lane = tid & 31;
    const int g = lane >> 2, c = lane & 3;
    const int m0 = wid * 32;

    const float* Qp = Q + ((size_t)bh * CT + q0) * 64;
    const float* Kp = K + (size_t)bh * CT * 64;
    const float* Vp = V + (size_t)bh * CT * 64;
    float* Op = O + ((size_t)bh * CT + q0) * 64;

    // ---- kick off tile 0 into buffer 0 (K0/V0) ----
    {
        const float* Kt = Kp;
        const float* Vt = Vp;
#pragma unroll
        for (int k = 0; k < 8; k++) {
            int i = tid + k * 128;
            int r = i >> 4, c4 = i & 15;
            unsigned off = (unsigned)(r * AST + c4 * 4) * 4u;
            cp_async16(sbase + off, Kt + r * 64 + c4 * 4);
            cp_async16(sbase + TILE_W * 4u + off, Vt + r * 64 + c4 * 4);
        }
        CP_COMMIT();
    }

    // ---- stage Q tile into K1/V1 area (8704 words), overlapping tile-0 dma
    {
        float* Qstage = (float*)(sm + 2 * TILE_W);
#pragma unroll
        for (int k = 0; k < 16; k++) {
            int i = tid + k * 128;
            int r = i >> 4, c4 = i & 15;
            float4 v = *(const float4*)(Qp + r * 64 + c4 * 4);
            *(float4*)&Qstage[r * AST + c4 * 4] = v;
        }
        __syncthreads();
    }
    // ---- build Q A-frags: half0 in regs, half1 in Qpk (thread-private slot)
    unsigned qa[8][4];
    {
        const float* Qstage = (const float*)(sm + 2 * TILE_W);
        const float qscale = 1.4426950408889634f / 256.0f;  // log2(e)/(8*32)
#pragma unroll
        for (int kc = 0; kc < 8; kc++) {
            qa[kc][0] = f2tf32(Qstage[(m0 + g)     * AST + kc * 8 + c]     * qscale);
            qa[kc][1] = f2tf32(Qstage[(m0 + g + 8) * AST + kc * 8 + c]     * qscale);
            qa[kc][2] = f2tf32(Qstage[(m0 + g)     * AST + kc * 8 + c + 4] * qscale);
            qa[kc][3] = f2tf32(Qstage[(m0 + g + 8) * AST + kc * 8 + c + 4] * qscale);
            uint4 qb;
            qb.x = f2tf32(Qstage[(m0 + g + 16) * AST + kc * 8 + c]     * qscale);
            qb.y = f2tf32(Qstage[(m0 + g + 24) * AST + kc * 8 + c]     * qscale);
            qb.z = f2tf32(Qstage[(m0 + g + 16) * AST + kc * 8 + c + 4] * qscale);
            qb.w = f2tf32(Qstage[(m0 + g + 24) * AST + kc * 8 + c + 4] * qscale);
            *(uint4*)&Qpk[((wid * 8 + kc) * 32 + lane) * 4] = qb;
        }
    }

    float oacc0[8][4], oacc1[8][4];
#pragma unroll
    for (int nb = 0; nb < 8; nb++)
#pragma unroll
        for (int k = 0; k < 4; k++) { oacc0[nb][k] = 0.f; oacc1[nb][k] = 0.f; }
    float lacc00 = 0.f, lacc01 = 0.f, lacc10 = 0.f, lacc11 = 0.f;

    for (int kt = 0; kt < 16; kt++) {
        CP_WAIT0();            // tile kt landed (this thread's copies)
        __syncthreads();       // visibility + all warps done with prev compute

        // prefetch tile kt+1 into the other buffer
        if (kt < 15) {
            const float* Kt = Kp + (kt + 1) * 64 * 64;
            const float* Vt = Vp + (kt + 1) * 64 * 64;
            unsigned bofs = ((kt + 1) & 1) ? 2u * TILE_W * 4u : 0u;
#pragma unroll
            for (int k = 0; k < 8; k++) {
                int i = tid + k * 128;
                int r = i >> 4, c4 = i & 15;
                unsigned off = (unsigned)(r * AST + c4 * 4) * 4u;
                cp_async16(sbase + bofs + off, Kt + r * 64 + c4 * 4);
                cp_async16(sbase + bofs + TILE_W * 4u + off, Vt + r * 64 + c4 * 4);
            }
            CP_COMMIT();
        }

        const unsigned* Kr = sm + ((kt & 1) ? 2 * TILE_W : 0);
        const unsigned* Vr = Kr + TILE_W;

        // ---- S = Q @ K^T : raw K bits are pre-rounded tf32 ----
        float s0[8][4], s1[8][4];
#pragma unroll
        for (int nb = 0; nb < 8; nb++)
#pragma unroll
            for (int k = 0; k < 4; k++) { s0[nb][k] = 0.f; s1[nb][k] = 0.f; }
#pragma unroll
        for (int kc = 0; kc < 8; kc++) {
            uint4 qb = *(const uint4*)&Qpk[((wid * 8 + kc) * 32 + lane) * 4];
#pragma unroll
            for (int nb = 0; nb < 8; nb++) {
                unsigned b0 = Kr[(nb * 8 + g) * AST + kc * 8 + c];
                unsigned b1 = Kr[(nb * 8 + g) * AST + kc * 8 + c + 4];
                mma_tf32(s0[nb], qa[kc][0], qa[kc][1], qa[kc][2], qa[kc][3], b0, b1);
                mma_tf32(s1[nb], qb.x, qb.y, qb.z, qb.w, b0, b1);
            }
        }

        // ---- max-free softmax: P = 2^s (log2e folded into qscale) ----
#pragma unroll
        for (int nb = 0; nb < 8; nb++) {
            s0[nb][0] = ex2_fast(s0[nb][0]); lacc00 += s0[nb][0];
            s0[nb][1] = ex2_fast(s0[nb][1]); lacc00 += s0[nb][1];
            s0[nb][2] = ex2_fast(s0[nb][2]); lacc01 += s0[nb][2];
            s0[nb][3] = ex2_fast(s0[nb][3]); lacc01 += s0[nb][3];
            s1[nb][0] = ex2_fast(s1[nb][0]); lacc10 += s1[nb][0];
            s1[nb][1] = ex2_fast(s1[nb][1]); lacc10 += s1[nb][1];
            s1[nb][2] = ex2_fast(s1[nb][2]); lacc11 += s1[nb][2];
            s1[nb][3] = ex2_fast(s1[nb][3]); lacc11 += s1[nb][3];
        }

        // ---- O += P @ V : P transposed C-frag -> A-frag via shfl ----
#pragma unroll
        for (int jc = 0; jc < 8; jc++) {
            const int srcA = (lane & ~3) | (c >> 1);
            const int srcB = srcA + 2;
            float t0, t1;
            unsigned pa0, pa1, pa2, pa3, pb0, pb1, pb2, pb3;
            t0 = __shfl_sync(0xffffffffu, s0[jc][0], srcA);
            t1 = __shfl_sync(0xffffffffu, s0[jc][1], srcA);
            pa0 = f2tf32((c & 1) ? t1 : t0);
            t0 = __shfl_sync(0xffffffffu, s0[jc][2], srcA);
            t1 = __shfl_sync(0xffffffffu, s0[jc][3], srcA);
            pa1 = f2tf32((c & 1) ? t1 : t0);
            t0 = __shfl_sync(0xffffffffu, s0[jc][0], srcB);
            t1 = __shfl_sync(0xffffffffu, s0[jc][1], srcB);
            pa2 = f2tf32((c & 1) ? t1 : t0);
            t0 = __shfl_sync(0xffffffffu, s0[jc][2], srcB);
            t1 = __shfl_sync(0xffffffffu, s0[jc][3], srcB);
            pa3 = f2tf32((c & 1) ? t1 : t0);

            t0 = __shfl_sync(0xffffffffu, s1[jc][0], srcA);
            t1 = __shfl_sync(0xffffffffu, s1[jc][1], srcA);
            pb0 = f2tf32((c & 1) ? t1 : t0);
            t0 = __shfl_sync(0xffffffffu, s1[jc][2], srcA);
            t1 = __shfl_sync(0xffffffffu, s1[jc][3], srcA);
            pb1 = f2tf32((c & 1) ? t1 : t0);
            t0 = __shfl_sync(0xffffffffu, s1[jc][0], srcB);
            t1 = __shfl_sync(0xffffffffu, s1[jc][1], srcB);
            pb2 = f2tf32((c & 1) ? t1 : t0);
            t0 = __shfl_sync(0xffffffffu, s1[jc][2], srcB);
            t1 = __shfl_sync(0xffffffffu, s1[jc][3], srcB);
            pb3 = f2tf32((c & 1) ? t1 : t0);

#pragma unroll
            for (int nb = 0; nb < 8; nb++) {
                unsigned vb0 = Vr[(jc * 8 + c)     * AST + nb * 8 + g];
                unsigned vb1 = Vr[(jc * 8 + c + 4) * AST + nb * 8 + g];
                mma_tf32(oacc0[nb], pa0, pa1, pa2, pa3, vb0, vb1);
                mma_tf32(oacc1[nb], pb0, pb1, pb2, pb3, vb0, vb1);
            }
        }
    }

    // ---- epilogue: reduce l across the 4-thread column groups, normalize ----
    float l00 = lacc00, l01 = lacc01, l10 = lacc10, l11 = lacc11;
#pragma unroll
    for (int off = 1; off <= 2; off <<= 1) {
        l00 += __shfl_xor_sync(0xffffffffu, l00, off);
        l01 += __shfl_xor_sync(0xffffffffu, l01, off);
        l10 += __shfl_xor_sync(0xffffffffu, l10, off);
        l11 += __shfl_xor_sync(0xffffffffu, l11, off);
    }
    float i00 = 1.f / l00, i01 = 1.f / l01, i10 = 1.f / l10, i11 = 1.f / l11;
#pragma unroll
    for (int nb = 0; nb < 8; nb++) {
        *(float2*)(Op + (size_t)(m0 + g)      * 64 + nb * 8 + 2 * c) = make_float2(oacc0[nb][0] * i00, oacc0[nb][1] * i00);
        *(float2*)(Op + (size_t)(m0 + g + 8)  * 64 + nb * 8 + 2 * c) = make_float2(oacc0[nb][2] * i01, oacc0[nb][3] * i01);
        *(float2*)(Op + (size_t)(m0 + g + 16) * 64 + nb * 8 + 2 * c) = make_float2(oacc1[nb][0] * i10, oacc1[nb][1] * i10);
        *(float2*)(Op + (size_t)(m0 + g + 24) * 64 + nb * 8 + 2 * c) = make_float2(oacc1[nb][2] * i11, oacc1[nb][3] * i11);
    }
}

// ---------------------------------------------------------------------------
extern "C" void kernel_launch(void* const* d_in, const int* in_sizes, int n_in,
                              void* d_out, int out_size)
{
    (void)in_sizes; (void)n_in; (void)out_size;
    const float* source = (const float*)d_in[0];
    const float* target = (const float*)d_in[1];
    const float* W_q    = (const float*)d_in[2];
    const float* W_v    = (const float*)d_in[3];
    const float* W_o    = (const float*)d_in[4];
    const float* W_ih   = (const float*)d_in[5];
    const float* W_hh   = (const float*)d_in[6];
    const float* b_ih   = (const float*)d_in[7];
    const float* b_hh   = (const float*)d_in[8];
    float* out = (float*)d_out;

    void *pQ, *pV, *pNW, *pATT;
    cudaGetSymbolAddress(&pQ,  g_Q);
    cudaGetSymbolAddress(&pV,  g_V);
    cudaGetSymbolAddress(&pNW, g_NW);
    cudaGetSymbolAddress(&pATT, g_ATT);
    float* Qb   = (float*)pQ;
    float* Vb   = (float*)pV;
    float* NWb  = (float*)pNW;
    float* ATTb = (float*)pATT;

    const int proj_smem = (128 * 68 + 64 * 68) * (int)sizeof(float);   // 52224
    cudaFuncSetAttribute(proj_mma_kernel,
                         cudaFuncAttributeMaxDynamicSharedMemorySize, proj_smem);
    const int attn_smem = SM_ATTN_WORDS * (int)sizeof(unsigned);       // 86016
    cudaFuncSetAttribute(attn_mma_kernel,
                         cudaFuncAttributeMaxDynamicSharedMemorySize, attn_smem);

    const dim3 pgrid(CT / 128, CB * CH);

    // V rounded to tf32 at production; Q rounded inside attn; O full fp32.
    proj_mma_kernel<<<pgrid, 128, proj_smem>>>(source, W_q, Qb, CE, 64, 1, 0, 0);
    proj_mma_kernel<<<pgrid, 128, proj_smem>>>(target, W_v, Vb, CE, 64, 1, 0, 1);

    rnn_kernel<<<CB * CH, 128>>>(target, W_ih, W_hh, b_ih, b_hh, NWb);

    attn_mma_kernel<<<pgrid, 128, attn_smem>>>(Qb, NWb, Vb, ATTb);

    proj_mma_kernel<<<pgrid, 128, proj_smem>>>(ATTb, W_o, out, 64, CE, 0, 1, 0);
}